// round 1
// baseline (speedup 1.0000x reference)
#include <cuda_runtime.h>

// Shapes (fixed by the problem): B=4, N=8, M=64, F=128, D=128
#define BN_TOT 32
#define M_DIM  64
#define F_DIM  128
#define D_DIM  128
#define EPS_LN 1e-5f

// Scratch for stage-1 results: P (which=0), Q (which=1), R (which=2),
// each [32][64][128] fp32. 3 MB total. Static __device__ array (no allocs).
__device__ float g_scratch[3 * BN_TOT * M_DIM * F_DIM];

// ---------------------------------------------------------------------------
// Stage 1: per (b,n) compute
//   P[i][f] = x_i . W1[f,128:256] + mean . W1[f,512:640] + b1[f]
//   Q[j][f] = x_j . W1[f,256:384]
//   R[i][f] = x_i . W1[f,  0:128] + mean . W1[f,384:512]
// grid = (32, 3): blockIdx.y selects which of {P,Q,R}.
// ---------------------------------------------------------------------------
__global__ void hoe_stage1(const float* __restrict__ x,
                           const float* __restrict__ W1,
                           const float* __restrict__ b1) {
    extern __shared__ float sm[];
    float* xs     = sm;                     // 64*128
    float* wt     = xs + M_DIM * F_DIM;     // 128*129 (transposed W1 chunk, padded)
    float* mean_s = wt + F_DIM * 129;       // 128
    float* mv_s   = mean_s + F_DIM;         // 128

    const int bn    = blockIdx.x;
    const int which = blockIdx.y;           // 0:P 1:Q 2:R
    const int tid   = threadIdx.x;

    // Load x tile [64][128]
    const float* xb = x + bn * (M_DIM * F_DIM);
    for (int idx = tid; idx < M_DIM * F_DIM; idx += 256) xs[idx] = xb[idx];
    __syncthreads();

    // Column mean over i (threads 0..127)
    if (tid < F_DIM) {
        float s = 0.f;
        #pragma unroll 8
        for (int i2 = 0; i2 < M_DIM; i2++) s += xs[i2 * F_DIM + tid];
        mean_s[tid] = s * (1.0f / M_DIM);
    }

    // Load main W1 chunk transposed into smem: wt[k][f] = W1[f, off+k]
    const int off_main = (which == 0) ? 128 : (which == 1) ? 256 : 0;
    __syncthreads();
    for (int idx = tid; idx < F_DIM * F_DIM; idx += 256) {
        const int f = idx >> 7, k = idx & 127;
        wt[k * 129 + f] = W1[f * 640 + off_main + k];
    }
    __syncthreads();

    // GEMM: out[i][f] = sum_k xs[i][k] * wt[k][f]
    // thread tile: 8 i x 4 f. warp = i-block, lanes span f.
    const int ty = tid >> 5, tx = tid & 31;
    float acc[8][4];
    #pragma unroll
    for (int ii = 0; ii < 8; ii++)
        #pragma unroll
        for (int ff = 0; ff < 4; ff++) acc[ii][ff] = 0.f;

    for (int k = 0; k < F_DIM; k += 4) {
        float4 xv[8];
        #pragma unroll
        for (int ii = 0; ii < 8; ii++)
            xv[ii] = *(const float4*)&xs[(ty * 8 + ii) * F_DIM + k];
        #pragma unroll
        for (int kk = 0; kk < 4; kk++) {
            const float w0 = wt[(k + kk) * 129 + tx];
            const float w1 = wt[(k + kk) * 129 + tx + 32];
            const float w2 = wt[(k + kk) * 129 + tx + 64];
            const float w3 = wt[(k + kk) * 129 + tx + 96];
            #pragma unroll
            for (int ii = 0; ii < 8; ii++) {
                const float xk = (kk == 0) ? xv[ii].x : (kk == 1) ? xv[ii].y
                               : (kk == 2) ? xv[ii].z : xv[ii].w;
                acc[ii][0] = fmaf(xk, w0, acc[ii][0]);
                acc[ii][1] = fmaf(xk, w1, acc[ii][1]);
                acc[ii][2] = fmaf(xk, w2, acc[ii][2]);
                acc[ii][3] = fmaf(xk, w3, acc[ii][3]);
            }
        }
    }

    // Second chunk (mean projection) for P (W1e @ 512) and R (W1d @ 384)
    if (which != 1) {
        const int off2 = (which == 0) ? 512 : 384;
        __syncthreads();
        for (int idx = tid; idx < F_DIM * F_DIM; idx += 256) {
            const int f = idx >> 7, k = idx & 127;
            wt[k * 129 + f] = W1[f * 640 + off2 + k];
        }
        __syncthreads();
        if (tid < F_DIM) {
            float s = 0.f;
            #pragma unroll 8
            for (int k = 0; k < F_DIM; k++) s = fmaf(mean_s[k], wt[k * 129 + tid], s);
            mv_s[tid] = s;
        }
        __syncthreads();
    }

    float* outp = g_scratch + which * (BN_TOT * M_DIM * F_DIM) + bn * (M_DIM * F_DIM);
    #pragma unroll
    for (int ff = 0; ff < 4; ff++) {
        const int f = tx + 32 * ff;
        float extra = 0.f;
        if (which != 1) extra += mv_s[f];
        if (which == 0) extra += b1[f];
        #pragma unroll
        for (int ii = 0; ii < 8; ii++)
            outp[(ty * 8 + ii) * F_DIM + f] = acc[ii][ff] + extra;
    }
}

// ---------------------------------------------------------------------------
// Stage 2: one block per (bn, i). Build h_pre[j][f] = P[i]+Q[j]+(i==j)R[i],
// LayerNorm over f, ReLU, +bias_p on diagonal, then out[j][d] = h.W2^T + b2.
// ---------------------------------------------------------------------------
// W2 stored interleaved by f-groups of 4 with padded group stride 520 floats:
//   element (d, f) at W2c[(f>>2)*520 + d*4 + (f&3)]
// -> GEMM-side float4 reads are 16B aligned & conflict-free.
#define W2C_STRIDE 520

__global__ void hoe_stage2(const float* __restrict__ gamma,
                           const float* __restrict__ beta,
                           const float* __restrict__ bias_p,
                           const float* __restrict__ W2,
                           const float* __restrict__ b2,
                           float* __restrict__ out) {
    extern __shared__ float sm[];
    float* W2c = sm;                        // 32*520 = 16640
    float* Qs  = W2c + 32 * W2C_STRIDE;     // 64*128 = 8192
    float* hs  = Qs + M_DIM * F_DIM;        // 64*128 = 8192 (16B-aligned base)
    float* Pv  = hs + M_DIM * F_DIM;        // 128
    float* Rv  = Pv + F_DIM;                // 128
    float* gv  = Rv + F_DIM;                // 128
    float* bv  = gv + F_DIM;                // 128
    float* bpv = bv + F_DIM;                // 128
    float* b2v = bpv + F_DIM;               // 128

    const int bid = blockIdx.x;
    const int bn  = bid >> 6;
    const int i   = bid & 63;
    const int tid = threadIdx.x;

    // Load W2 into interleaved smem layout
    for (int idx = tid; idx < D_DIM * F_DIM; idx += 256) {
        const int d = idx >> 7, f = idx & 127;
        W2c[(f >> 2) * W2C_STRIDE + d * 4 + (f & 3)] = W2[idx];
    }
    // Load Q tile for this (b,n)
    const float* Qg = g_scratch + 1 * (BN_TOT * M_DIM * F_DIM) + bn * (M_DIM * F_DIM);
    for (int idx = tid; idx < M_DIM * F_DIM; idx += 256) Qs[idx] = Qg[idx];
    // Load per-row vectors
    if (tid < F_DIM) {
        Pv[tid]  = g_scratch[0 * (BN_TOT * M_DIM * F_DIM) + bn * (M_DIM * F_DIM) + i * F_DIM + tid];
        Rv[tid]  = g_scratch[2 * (BN_TOT * M_DIM * F_DIM) + bn * (M_DIM * F_DIM) + i * F_DIM + tid];
        gv[tid]  = gamma[tid];
        bv[tid]  = beta[tid];
        bpv[tid] = bias_p[tid];
        b2v[tid] = b2[tid];
    }
    __syncthreads();

    // --- LayerNorm + ReLU phase: warp w handles rows j = w*8 .. w*8+7 ---
    const int w    = tid >> 5;
    const int lane = tid & 31;
    for (int r = 0; r < 8; r++) {
        const int j = w * 8 + r;
        float v[4];
        float s = 0.f;
        #pragma unroll
        for (int q = 0; q < 4; q++) {
            const int f = lane + 32 * q;
            float t = Pv[f] + Qs[j * F_DIM + f];
            if (j == i) t += Rv[f];
            v[q] = t;
            s += t;
        }
        #pragma unroll
        for (int o = 16; o > 0; o >>= 1) s += __shfl_xor_sync(0xffffffffu, s, o);
        const float mu = s * (1.0f / F_DIM);
        float ss = 0.f;
        #pragma unroll
        for (int q = 0; q < 4; q++) { const float d0 = v[q] - mu; v[q] = d0; ss += d0 * d0; }
        #pragma unroll
        for (int o = 16; o > 0; o >>= 1) ss += __shfl_xor_sync(0xffffffffu, ss, o);
        const float rstd = rsqrtf(ss * (1.0f / F_DIM) + EPS_LN);
        #pragma unroll
        for (int q = 0; q < 4; q++) {
            const int f = lane + 32 * q;
            float hv = fmaf(v[q] * rstd, gv[f], bv[f]);
            hv = fmaxf(hv, 0.f);
            if (j == i) hv += bpv[f];
            hs[j * F_DIM + f] = hv;
        }
    }
    __syncthreads();

    // --- GEMM phase: out[j][d] = sum_f hs[j][f] * W2[d][f] + b2[d] ---
    // thread tile: 8 j x 4 d; warp w owns j rows w*8..w*8+7 (broadcast h reads)
    float acc[8][4];
    #pragma unroll
    for (int jj = 0; jj < 8; jj++)
        #pragma unroll
        for (int dd = 0; dd < 4; dd++) acc[jj][dd] = 0.f;

    #pragma unroll 4
    for (int g = 0; g < 32; g++) {
        float4 wv[4];
        #pragma unroll
        for (int dd = 0; dd < 4; dd++)
            wv[dd] = *(const float4*)&W2c[g * W2C_STRIDE + (lane + 32 * dd) * 4];
        #pragma unroll
        for (int jj = 0; jj < 8; jj++) {
            const float4 hv4 = *(const float4*)&hs[(w * 8 + jj) * F_DIM + g * 4];
            #pragma unroll
            for (int dd = 0; dd < 4; dd++) {
                acc[jj][dd] = fmaf(hv4.x, wv[dd].x, acc[jj][dd]);
                acc[jj][dd] = fmaf(hv4.y, wv[dd].y, acc[jj][dd]);
                acc[jj][dd] = fmaf(hv4.z, wv[dd].z, acc[jj][dd]);
                acc[jj][dd] = fmaf(hv4.w, wv[dd].w, acc[jj][dd]);
            }
        }
    }

    float* outb = out + (size_t)bid * (M_DIM * D_DIM);
    #pragma unroll
    for (int jj = 0; jj < 8; jj++) {
        const int j = w * 8 + jj;
        #pragma unroll
        for (int dd = 0; dd < 4; dd++) {
            const int d = lane + 32 * dd;
            outb[j * D_DIM + d] = acc[jj][dd] + b2v[d];
        }
    }
}

// ---------------------------------------------------------------------------
extern "C" void kernel_launch(void* const* d_in, const int* in_sizes, int n_in,
                              void* d_out, int out_size) {
    const float* x      = (const float*)d_in[0];
    const float* W1     = (const float*)d_in[1];
    const float* b1     = (const float*)d_in[2];
    const float* gamma  = (const float*)d_in[3];
    const float* beta   = (const float*)d_in[4];
    const float* bias_p = (const float*)d_in[5];
    const float* W2     = (const float*)d_in[6];
    const float* b2     = (const float*)d_in[7];
    float* out          = (float*)d_out;

    const int smem1 = (M_DIM * F_DIM + F_DIM * 129 + 2 * F_DIM) * (int)sizeof(float);      // ~99.8 KB
    const int smem2 = (32 * W2C_STRIDE + 2 * M_DIM * F_DIM + 6 * F_DIM) * (int)sizeof(float); // ~135 KB

    cudaFuncSetAttribute(hoe_stage1, cudaFuncAttributeMaxDynamicSharedMemorySize, smem1);
    cudaFuncSetAttribute(hoe_stage2, cudaFuncAttributeMaxDynamicSharedMemorySize, smem2);

    dim3 grid1(BN_TOT, 3);
    hoe_stage1<<<grid1, 256, smem1>>>(x, W1, b1);
    hoe_stage2<<<BN_TOT * M_DIM, 256, smem2>>>(gamma, beta, bias_p, W2, b2, out);
}

// round 4
// speedup vs baseline: 1.6251x; 1.6251x over previous
#include <cuda_runtime.h>
#include <cstdint>

// Shapes (fixed): B=4, N=8, M=64, F=128, D=128
#define BN_TOT 32
#define M_DIM  64
#define F_DIM  128
#define D_DIM  128
#define EPS_LN 1e-5f

// Scratch: P (which=0), Q (which=1), R (which=2), each [32][64][128] fp32.
__device__ float g_scratch[3 * BN_TOT * M_DIM * F_DIM];

// ---------------------------------------------------------------------------
// Stage 1 (unchanged): per (b,n) compute P/Q/R linear projections.
// ---------------------------------------------------------------------------
__global__ void hoe_stage1(const float* __restrict__ x,
                           const float* __restrict__ W1,
                           const float* __restrict__ b1) {
    extern __shared__ float sm[];
    float* xs     = sm;                     // 64*128
    float* wt     = xs + M_DIM * F_DIM;     // 128*129
    float* mean_s = wt + F_DIM * 129;       // 128
    float* mv_s   = mean_s + F_DIM;         // 128

    const int bn    = blockIdx.x;
    const int which = blockIdx.y;           // 0:P 1:Q 2:R
    const int tid   = threadIdx.x;

    const float* xb = x + bn * (M_DIM * F_DIM);
    for (int idx = tid; idx < M_DIM * F_DIM; idx += 256) xs[idx] = xb[idx];
    __syncthreads();

    if (tid < F_DIM) {
        float s = 0.f;
        #pragma unroll 8
        for (int i2 = 0; i2 < M_DIM; i2++) s += xs[i2 * F_DIM + tid];
        mean_s[tid] = s * (1.0f / M_DIM);
    }

    const int off_main = (which == 0) ? 128 : (which == 1) ? 256 : 0;
    __syncthreads();
    for (int idx = tid; idx < F_DIM * F_DIM; idx += 256) {
        const int f = idx >> 7, k = idx & 127;
        wt[k * 129 + f] = W1[f * 640 + off_main + k];
    }
    __syncthreads();

    const int ty = tid >> 5, tx = tid & 31;
    float acc[8][4];
    #pragma unroll
    for (int ii = 0; ii < 8; ii++)
        #pragma unroll
        for (int ff = 0; ff < 4; ff++) acc[ii][ff] = 0.f;

    for (int k = 0; k < F_DIM; k += 4) {
        float4 xv[8];
        #pragma unroll
        for (int ii = 0; ii < 8; ii++)
            xv[ii] = *(const float4*)&xs[(ty * 8 + ii) * F_DIM + k];
        #pragma unroll
        for (int kk = 0; kk < 4; kk++) {
            const float w0 = wt[(k + kk) * 129 + tx];
            const float w1 = wt[(k + kk) * 129 + tx + 32];
            const float w2 = wt[(k + kk) * 129 + tx + 64];
            const float w3 = wt[(k + kk) * 129 + tx + 96];
            #pragma unroll
            for (int ii = 0; ii < 8; ii++) {
                const float xk = (kk == 0) ? xv[ii].x : (kk == 1) ? xv[ii].y
                               : (kk == 2) ? xv[ii].z : xv[ii].w;
                acc[ii][0] = fmaf(xk, w0, acc[ii][0]);
                acc[ii][1] = fmaf(xk, w1, acc[ii][1]);
                acc[ii][2] = fmaf(xk, w2, acc[ii][2]);
                acc[ii][3] = fmaf(xk, w3, acc[ii][3]);
            }
        }
    }

    if (which != 1) {
        const int off2 = (which == 0) ? 512 : 384;
        __syncthreads();
        for (int idx = tid; idx < F_DIM * F_DIM; idx += 256) {
            const int f = idx >> 7, k = idx & 127;
            wt[k * 129 + f] = W1[f * 640 + off2 + k];
        }
        __syncthreads();
        if (tid < F_DIM) {
            float s = 0.f;
            #pragma unroll 8
            for (int k = 0; k < F_DIM; k++) s = fmaf(mean_s[k], wt[k * 129 + tid], s);
            mv_s[tid] = s;
        }
        __syncthreads();
    }

    float* outp = g_scratch + which * (BN_TOT * M_DIM * F_DIM) + bn * (M_DIM * F_DIM);
    #pragma unroll
    for (int ff = 0; ff < 4; ff++) {
        const int f = tx + 32 * ff;
        float extra = 0.f;
        if (which != 1) extra += mv_s[f];
        if (which == 0) extra += b1[f];
        #pragma unroll
        for (int ii = 0; ii < 8; ii++)
            outp[(ty * 8 + ii) * F_DIM + f] = acc[ii][ff] + extra;
    }
}

// ---------------------------------------------------------------------------
// Stage 2: warp-level bf16 MMA (mma.sync m16n8k16 — base-ISA, no 'a' features)
// One block per (bn, i-pair): M=128 rows (2 i x 64 j), N=128 (d), K=128 (f),
// 3-term bf16 split folded into one K=384 loop over slab pairs.
// ---------------------------------------------------------------------------

// SMEM slabs: 128 rows x 128 bf16 (256 B/row), XOR-swizzled in 16B chunks.
#define AHI 0
#define ALO 32768
#define BHI 65536
#define BLO 98304
#define VECO 131072
#define SMEM2_BYTES 135168

static __device__ __forceinline__ uint32_t cvta_smem(const void* p) {
    uint32_t a;
    asm("{ .reg .u64 t; cvta.to.shared.u64 t, %1; cvt.u32.u64 %0, t; }"
        : "=r"(a) : "l"(p));
    return a;
}
// pack bf16(lo), bf16(hi): lo in low 16 bits
static __device__ __forceinline__ uint32_t packbf(float lo, float hi) {
    uint32_t r;
    asm("cvt.rn.bf16x2.f32 %0, %1, %2;" : "=r"(r) : "f"(hi), "f"(lo));
    return r;
}
// swizzled byte offset within a slab: row in [0,128), kbyte in [0,256)
static __device__ __forceinline__ uint32_t swz(uint32_t row, uint32_t kbyte) {
    return row * 256u + ((((kbyte >> 4) ^ (row & 7u)) << 4) | (kbyte & 15u));
}
static __device__ __forceinline__ void ldsm4(uint32_t* r, uint32_t addr) {
    asm volatile("ldmatrix.sync.aligned.m8n8.x4.shared.b16 {%0,%1,%2,%3}, [%4];"
                 : "=r"(r[0]), "=r"(r[1]), "=r"(r[2]), "=r"(r[3]) : "r"(addr));
}
static __device__ __forceinline__ void mma16816(float* c, const uint32_t* a,
                                                uint32_t b0, uint32_t b1) {
    asm volatile(
        "mma.sync.aligned.m16n8k16.row.col.f32.bf16.bf16.f32 "
        "{%0,%1,%2,%3}, {%4,%5,%6,%7}, {%8,%9}, {%0,%1,%2,%3};"
        : "+f"(c[0]), "+f"(c[1]), "+f"(c[2]), "+f"(c[3])
        : "r"(a[0]), "r"(a[1]), "r"(a[2]), "r"(a[3]), "r"(b0), "r"(b1));
}

__global__ void __launch_bounds__(256, 1)
hoe_stage2_mma(const float* __restrict__ gamma,
               const float* __restrict__ beta,
               const float* __restrict__ bias_p,
               const float* __restrict__ W2,
               const float* __restrict__ b2,
               float* __restrict__ out) {
    extern __shared__ char smem[];
    float* Pv  = (float*)(smem + VECO);      // [2][128]
    float* Rv  = Pv + 256;                   // [2][128]
    float* gv  = Rv + 256;
    float* bv  = gv + 128;
    float* bpv = bv + 128;
    float* b2v = bpv + 128;

    const uint32_t sbase = cvta_smem(smem);
    const int tid  = threadIdx.x;
    const int lane = tid & 31;
    const int wid  = tid >> 5;
    const int bid  = blockIdx.x;
    const int bn   = bid >> 5;
    const int i0   = (bid & 31) * 2;

    // Per-block vectors
    if (tid < 128) {
        const int pofs = bn * (M_DIM * F_DIM);
        Pv[tid]       = g_scratch[0 * (BN_TOT * M_DIM * F_DIM) + pofs + (i0    ) * F_DIM + tid];
        Pv[128 + tid] = g_scratch[0 * (BN_TOT * M_DIM * F_DIM) + pofs + (i0 + 1) * F_DIM + tid];
        Rv[tid]       = g_scratch[2 * (BN_TOT * M_DIM * F_DIM) + pofs + (i0    ) * F_DIM + tid];
        Rv[128 + tid] = g_scratch[2 * (BN_TOT * M_DIM * F_DIM) + pofs + (i0 + 1) * F_DIM + tid];
        gv[tid]  = gamma[tid];
        bv[tid]  = beta[tid];
        bpv[tid] = bias_p[tid];
        b2v[tid] = b2[tid];
    }

    // Convert W2 -> bf16 hi/lo slabs (swizzled, row = d, kbyte = f*2)
    for (int idx = tid; idx < 4096; idx += 256) {
        const int d  = idx >> 5;
        const int cw = idx & 31;              // covers f4 = cw*4 floats
        const float4 v = __ldg((const float4*)(W2 + d * 128 + cw * 4));
        const uint32_t hiA = packbf(v.x, v.y);
        const uint32_t hiB = packbf(v.z, v.w);
        const float r0 = v.x - __uint_as_float(hiA << 16);
        const float r1 = v.y - __uint_as_float(hiA & 0xffff0000u);
        const float r2 = v.z - __uint_as_float(hiB << 16);
        const float r3 = v.w - __uint_as_float(hiB & 0xffff0000u);
        const uint32_t loA = packbf(r0, r1);
        const uint32_t loB = packbf(r2, r3);
        const uint32_t off = swz((uint32_t)d, (uint32_t)cw * 8u);
        *(uint2*)(smem + BHI + off) = make_uint2(hiA, hiB);
        *(uint2*)(smem + BLO + off) = make_uint2(loA, loB);
    }
    __syncthreads();

    // LayerNorm + ReLU + diag bias + bf16 split -> A slabs. 16 rows per warp.
    const float* Qg = g_scratch + 1 * (BN_TOT * M_DIM * F_DIM) + bn * (M_DIM * F_DIM);
    for (int r = 0; r < 16; r++) {
        const int m   = wid * 16 + r;
        const int sel = m >> 6;
        const int j   = m & 63;
        const int f4  = lane * 4;
        const bool diag = (j == i0 + sel);

        float4 q = __ldg((const float4*)(Qg + j * 128 + f4));
        float v0 = q.x + Pv[sel * 128 + f4 + 0];
        float v1 = q.y + Pv[sel * 128 + f4 + 1];
        float v2 = q.z + Pv[sel * 128 + f4 + 2];
        float v3 = q.w + Pv[sel * 128 + f4 + 3];
        if (diag) {
            v0 += Rv[sel * 128 + f4 + 0];
            v1 += Rv[sel * 128 + f4 + 1];
            v2 += Rv[sel * 128 + f4 + 2];
            v3 += Rv[sel * 128 + f4 + 3];
        }
        float s = v0 + v1 + v2 + v3;
        #pragma unroll
        for (int o = 16; o > 0; o >>= 1) s += __shfl_xor_sync(0xffffffffu, s, o);
        const float mu = s * (1.0f / F_DIM);
        v0 -= mu; v1 -= mu; v2 -= mu; v3 -= mu;
        float ss = v0 * v0 + v1 * v1 + v2 * v2 + v3 * v3;
        #pragma unroll
        for (int o = 16; o > 0; o >>= 1) ss += __shfl_xor_sync(0xffffffffu, ss, o);
        const float rstd = rsqrtf(ss * (1.0f / F_DIM) + EPS_LN);

        float h0 = fmaxf(fmaf(v0 * rstd, gv[f4 + 0], bv[f4 + 0]), 0.f);
        float h1 = fmaxf(fmaf(v1 * rstd, gv[f4 + 1], bv[f4 + 1]), 0.f);
        float h2 = fmaxf(fmaf(v2 * rstd, gv[f4 + 2], bv[f4 + 2]), 0.f);
        float h3 = fmaxf(fmaf(v3 * rstd, gv[f4 + 3], bv[f4 + 3]), 0.f);
        if (diag) { h0 += bpv[f4 + 0]; h1 += bpv[f4 + 1]; h2 += bpv[f4 + 2]; h3 += bpv[f4 + 3]; }

        const uint32_t hiA = packbf(h0, h1);
        const uint32_t hiB = packbf(h2, h3);
        const float r0 = h0 - __uint_as_float(hiA << 16);
        const float r1 = h1 - __uint_as_float(hiA & 0xffff0000u);
        const float r2 = h2 - __uint_as_float(hiB << 16);
        const float r3 = h3 - __uint_as_float(hiB & 0xffff0000u);
        const uint32_t loA = packbf(r0, r1);
        const uint32_t loB = packbf(r2, r3);
        const uint32_t off = swz((uint32_t)m, (uint32_t)lane * 8u);
        *(uint2*)(smem + AHI + off) = make_uint2(hiA, hiB);
        *(uint2*)(smem + ALO + off) = make_uint2(loA, loB);
    }
    __syncthreads();

    // --- MMA mainloop. Warp grid 2x4: warp tile 64(M) x 32(N). ---
    const int warpM = wid >> 2;               // 0..1
    const int warpN = wid & 3;                // 0..3
    const int q  = lane >> 3;                 // ldmatrix quadrant
    const int lr = lane & 7;

    // A ldmatrix lane row/chunk: matrices {rows0-7 klo, rows8-15 klo, rows0-7 khi, rows8-15 khi}
    const int rowA  = lr + ((q & 1) << 3);
    const int cselA = q >> 1;
    uint32_t rowOffA[4];
    #pragma unroll
    for (int mt = 0; mt < 4; mt++)
        rowOffA[mt] = (uint32_t)(warpM * 64 + mt * 16 + rowA) * 256u;

    // B ldmatrix lane row/chunk: matrices {n0-7 klo, n0-7 khi, n8-15 klo, n8-15 khi}
    const int rowB  = lr + ((q >> 1) << 3);
    const int cselB = q & 1;
    uint32_t rowOffB[2];
    #pragma unroll
    for (int np = 0; np < 2; np++)
        rowOffB[np] = (uint32_t)(warpN * 32 + np * 16 + rowB) * 256u;

    float acc[4][4][4];
    #pragma unroll
    for (int mt = 0; mt < 4; mt++)
        #pragma unroll
        for (int nt = 0; nt < 4; nt++)
            #pragma unroll
            for (int e = 0; e < 4; e++) acc[mt][nt][e] = 0.f;

    const uint32_t slabsA[3] = { sbase + AHI, sbase + ALO, sbase + AHI };
    const uint32_t slabsB[3] = { sbase + BHI, sbase + BHI, sbase + BLO };

    #pragma unroll
    for (int p = 0; p < 3; p++) {
        const uint32_t sa = slabsA[p];
        const uint32_t sb = slabsB[p];
        #pragma unroll
        for (int kk = 0; kk < 8; kk++) {
            const uint32_t kxA = (uint32_t)(((kk << 1) + cselA) ^ lr) << 4;
            const uint32_t kxB = (uint32_t)(((kk << 1) + cselB) ^ lr) << 4;
            uint32_t af[4][4], bf[2][4];
            #pragma unroll
            for (int mt = 0; mt < 4; mt++) ldsm4(af[mt], sa + rowOffA[mt] + kxA);
            #pragma unroll
            for (int np = 0; np < 2; np++) ldsm4(bf[np], sb + rowOffB[np] + kxB);
            #pragma unroll
            for (int mt = 0; mt < 4; mt++) {
                #pragma unroll
                for (int nt = 0; nt < 4; nt++) {
                    const int np = nt >> 1;
                    const int hb = (nt & 1) << 1;
                    mma16816(acc[mt][nt], af[mt], bf[np][hb], bf[np][hb + 1]);
                }
            }
        }
    }

    // Epilogue: add b2, store fp32 directly (32B segments fully covered)
    const int bnBase = (bn * 64 + i0) * 64;
    #pragma unroll
    for (int mt = 0; mt < 4; mt++) {
        #pragma unroll
        for (int half = 0; half < 2; half++) {
            const int m   = warpM * 64 + mt * 16 + (lane >> 2) + half * 8;
            const int sel = m >> 6;
            const int j   = m & 63;
            float* orow = out + ((size_t)(bnBase + sel * 64 + j)) * 128;
            #pragma unroll
            for (int nt = 0; nt < 4; nt++) {
                const int n = warpN * 32 + nt * 8 + (lane & 3) * 2;
                float2 v;
                v.x = acc[mt][nt][half * 2 + 0] + b2v[n];
                v.y = acc[mt][nt][half * 2 + 1] + b2v[n + 1];
                *(float2*)(orow + n) = v;
            }
        }
    }
}

// ---------------------------------------------------------------------------
extern "C" void kernel_launch(void* const* d_in, const int* in_sizes, int n_in,
                              void* d_out, int out_size) {
    const float* x      = (const float*)d_in[0];
    const float* W1     = (const float*)d_in[1];
    const float* b1     = (const float*)d_in[2];
    const float* gamma  = (const float*)d_in[3];
    const float* beta   = (const float*)d_in[4];
    const float* bias_p = (const float*)d_in[5];
    const float* W2     = (const float*)d_in[6];
    const float* b2     = (const float*)d_in[7];
    float* out          = (float*)d_out;

    const int smem1 = (M_DIM * F_DIM + F_DIM * 129 + 2 * F_DIM) * (int)sizeof(float);
    cudaFuncSetAttribute(hoe_stage1, cudaFuncAttributeMaxDynamicSharedMemorySize, smem1);
    cudaFuncSetAttribute(hoe_stage2_mma, cudaFuncAttributeMaxDynamicSharedMemorySize, SMEM2_BYTES);

    dim3 grid1(BN_TOT, 3);
    hoe_stage1<<<grid1, 256, smem1>>>(x, W1, b1);
    hoe_stage2_mma<<<BN_TOT * 32, 256, SMEM2_BYTES>>>(gamma, beta, bias_p, W2, b2, out);
}